// round 10
// baseline (speedup 1.0000x reference)
#include <cuda_runtime.h>
#include <math.h>
#include <stdint.h>

#define LDIM 4096
#define NPTS 2048
#define WPIX 640.0f
#define HPIX 480.0f
#define ROW_BYTES (NPTS * 2 * 4)   // 16384

__device__ __forceinline__ uint32_t smem_u32(const void* p)
{
    uint32_t a;
    asm("{ .reg .u64 t; cvta.to.shared.u64 t, %1; cvt.u32.u64 %0, t; }"
        : "=r"(a) : "l"(p));
    return a;
}

// ---------------------------------------------------------------------------
// Fused kernel: one block per l. A single 16KB cp.async.bulk (TMA) pulls the
// row into smem — bypassing the per-warp LDG/L1tex path that capped DRAM at
// ~59%. 128 threads then read conflict-free LDS.128, reduce 5 moments, and
// thread 0 runs the trig-free eigensolve.
// ---------------------------------------------------------------------------
__global__ void __launch_bounds__(128, 8)
fused_kernel(const float* __restrict__ in,
             const float* __restrict__ center,
             const float* __restrict__ alpha_p,
             float* __restrict__ out)
{
    __shared__ alignas(128) float4 tile[ROW_BYTES / 16];  // 16 KB
    __shared__ uint64_t mbar;

    const int l = blockIdx.x;
    const int t = threadIdx.x;

    const float cx = center[0];
    const float cy = center[1];
    const float alpha = alpha_p[0];
    const float invW = 1.0f / WPIX;
    const float invH = 1.0f / HPIX;

    const uint32_t tile_a = smem_u32(tile);
    const uint32_t mbar_a = smem_u32(&mbar);

    if (t == 0) {
        asm volatile("mbarrier.init.shared.b64 [%0], 1;" :: "r"(mbar_a) : "memory");
    }
    __syncthreads();

    if (t == 0) {
        const float* src = in + (size_t)l * (NPTS * 2);
        asm volatile("mbarrier.arrive.expect_tx.shared.b64 _, [%0], %1;"
                     :: "r"(mbar_a), "r"((uint32_t)ROW_BYTES) : "memory");
        asm volatile("cp.async.bulk.shared::cta.global.mbarrier::complete_tx::bytes "
                     "[%0], [%1], %2, [%3];"
                     :: "r"(tile_a), "l"(src), "r"((uint32_t)ROW_BYTES), "r"(mbar_a)
                     : "memory");
    }

    // Wait for the bulk copy (parity 0 — mbarrier reinitialized every launch).
    {
        uint32_t done;
        asm volatile(
            "{\n\t"
            ".reg .pred p;\n\t"
            "WAIT_%=:\n\t"
            "mbarrier.try_wait.parity.acquire.cta.shared::cta.b64 p, [%1], 0, 0x989680;\n\t"
            "selp.b32 %0, 1, 0, p;\n\t"
            "@!p bra.uni WAIT_%=;\n\t"
            "}"
            : "=r"(done) : "r"(mbar_a) : "memory");
    }

    float Sxx = 0.f, Sxy = 0.f, Syy = 0.f, Sx = 0.f, Sy = 0.f;

    #pragma unroll
    for (int k = 0; k < 8; k++) {
        float4 v = tile[t + k * 128];   // conflict-free LDS.128

        float sx = v.x * invW - cx;
        float sy = v.y * invH - cy;
        float r2 = sx * sx + sy * sy;
        float f  = 1.0f + alpha * r2;
        float ux = f * sx + cx;
        float uy = f * sy + cy;
        Sxx += ux * ux; Sxy += ux * uy; Syy += uy * uy; Sx += ux; Sy += uy;

        sx = v.z * invW - cx;
        sy = v.w * invH - cy;
        r2 = sx * sx + sy * sy;
        f  = 1.0f + alpha * r2;
        ux = f * sx + cx;
        uy = f * sy + cy;
        Sxx += ux * ux; Sxy += ux * uy; Syy += uy * uy; Sx += ux; Sy += uy;
    }

    #pragma unroll
    for (int o = 16; o > 0; o >>= 1) {
        Sxx += __shfl_xor_sync(0xffffffffu, Sxx, o);
        Sxy += __shfl_xor_sync(0xffffffffu, Sxy, o);
        Syy += __shfl_xor_sync(0xffffffffu, Syy, o);
        Sx  += __shfl_xor_sync(0xffffffffu, Sx,  o);
        Sy  += __shfl_xor_sync(0xffffffffu, Sy,  o);
    }

    __shared__ float sm[5];
    if (t < 5) sm[t] = 0.f;
    __syncthreads();
    if ((t & 31) == 0) {
        atomicAdd(&sm[0], Sxx);
        atomicAdd(&sm[1], Sxy);
        atomicAdd(&sm[2], Syy);
        atomicAdd(&sm[3], Sx);
        atomicAdd(&sm[4], Sy);
    }
    __syncthreads();

    if (t == 0) {
        // M = [[Sxx, Sxy, -Sx], [Sxy, Syy, -Sy], [-Sx, -Sy, N]]
        float m00 =  sm[0];
        float m01 =  sm[1];
        float m11 =  sm[2];
        float m02 = -sm[3];
        float m12 = -sm[4];
        float m22 =  (float)NPTS;

        // Newton on det(M - lam I) from lam = 0: monotone convergence for
        // SPD M with well-separated lam_min.
        float lam = 0.0f;
        #pragma unroll
        for (int it = 0; it < 6; it++) {
            float a00 = m00 - lam, a11 = m11 - lam, a22 = m22 - lam;
            float M0 = a11 * a22 - m12 * m12;
            float M1 = a00 * a22 - m02 * m02;
            float M2 = a00 * a11 - m01 * m01;
            float det = a00 * M0
                      - m01 * (m01 * a22 - m12 * m02)
                      + m02 * (m01 * m12 - a11 * m02);
            float dp = M0 + M1 + M2;           // = -p'(lam)
            lam += det / fmaxf(dp, 1e-20f);
        }

        // Eigenvector: largest cross product of rows of (M - lam I).
        float c00 = m00 - lam, c11 = m11 - lam, c22 = m22 - lam;

        float x0 = m01 * m12 - m02 * c11;
        float y0 = m02 * m01 - c00 * m12;
        float z0 = c00 * c11 - m01 * m01;
        float n0 = x0 * x0 + y0 * y0 + z0 * z0;

        float x1 = m01 * c22 - m02 * m12;
        float y1 = m02 * m02 - c00 * c22;
        float z1 = c00 * m12 - m01 * m02;
        float n1 = x1 * x1 + y1 * y1 + z1 * z1;

        float x2 = c11 * c22 - m12 * m12;
        float y2 = m12 * m02 - m01 * c22;
        float z2 = m01 * m12 - c11 * m02;
        float n2 = x2 * x2 + y2 * y2 + z2 * z2;

        float vx = x0, vy = y0, vz = z0, nbest = n0;
        if (n1 > nbest) { vx = x1; vy = y1; vz = z1; nbest = n1; }
        if (n2 > nbest) { vx = x2; vy = y2; vz = z2; nbest = n2; }

        // err = v^T M v / (vx^2 + vy^2)
        float vMv = m00 * vx * vx + m11 * vy * vy + m22 * vz * vz
                  + 2.0f * (m01 * vx * vy + m02 * vx * vz + m12 * vy * vz);
        float denom = vx * vx + vy * vy;
        out[l] = vMv / denom;
    }
}

extern "C" void kernel_launch(void* const* d_in, const int* in_sizes, int n_in,
                              void* d_out, int out_size)
{
    const float* input  = (const float*)d_in[0];
    const float* center = (const float*)d_in[1];
    const float* alpha  = (const float*)d_in[2];
    float* out = (float*)d_out;

    fused_kernel<<<LDIM, 128>>>(input, center, alpha, out);
}